// round 10
// baseline (speedup 1.0000x reference)
#include <cuda_runtime.h>
#include <math.h>

static constexpr int Bc  = 2;
static constexpr int Sc  = 2048;
static constexpr int Dc  = 1024;
static constexpr int Hc  = 16;
static constexpr int HDc = 64;
static constexpr int Mtot = Bc * Sc;   // 4096

// Scratch (device globals). All MMA operands are tf32-rounded bit patterns.
// Layouts are pair-interleaved so (k, k+4) fragment partners are adjacent:
//  g_xt / g_ctx : row-major rows of 1024, within-row perm
//                 k -> (k>>3)*8 + (k&3)*2 + ((k>>2)&1)
//  g_w*         : element (k,n) -> (k>>3)*8192 + (k&3)*2048 + n*2 + ((k>>2)&1)
//  g_k          : [bh][key][perm(hd)]   (same within-row perm as g_xt)
//  g_v          : [bh][key-tile t][slab][hd*2+half], slab=(w>>3)*4+(w&3),
//                 half=(w>>2)&1, w=key&31, t=key>>5   (slab row = 128 floats)
//  g_q          : plain [B,H,S,HD] tf32 bits
__device__ float g_q[(size_t)Bc * Hc * Sc * HDc];
__device__ float g_k[(size_t)Bc * Hc * Sc * HDc];
__device__ float g_v[(size_t)Bc * Hc * Sc * HDc];
__device__ float g_ctx[(size_t)Bc * Sc * Dc];
__device__ float g_xt[(size_t)Mtot * Dc];
__device__ float g_wq[(size_t)Dc * Dc];
__device__ float g_wk[(size_t)Dc * Dc];
__device__ float g_wv[(size_t)Dc * Dc];
__device__ float g_wo[(size_t)Dc * Dc];

// ---------------------------------------------------------------------------
__device__ __forceinline__ unsigned f2tf(float x) {
    unsigned r;
    asm("cvt.rna.tf32.f32 %0, %1;" : "=r"(r) : "f"(x));
    return r;
}
__device__ __forceinline__ float f2tfb(float x) { return __uint_as_float(f2tf(x)); }

__device__ __forceinline__ void mma8(float c[4], const unsigned a[4], const unsigned b[2]) {
    asm volatile(
        "mma.sync.aligned.m16n8k8.row.col.f32.tf32.tf32.f32 "
        "{%0,%1,%2,%3}, {%4,%5,%6,%7}, {%8,%9}, {%0,%1,%2,%3};"
        : "+f"(c[0]), "+f"(c[1]), "+f"(c[2]), "+f"(c[3])
        : "r"(a[0]), "r"(a[1]), "r"(a[2]), "r"(a[3]), "r"(b[0]), "r"(b[1]));
}

__device__ __forceinline__ void cpasync16(unsigned dst, const void* src) {
    asm volatile("cp.async.ca.shared.global [%0], [%1], 16;" :: "r"(dst), "l"(src));
}

// ---------------------------------------------------------------------------
// Convert x -> tf32 bits with within-row (k,k+4) interleave.
// ---------------------------------------------------------------------------
__global__ __launch_bounds__(256)
void xconv(const float* __restrict__ src, float* __restrict__ dst)
{
    const int id = blockIdx.x * 256 + threadIdx.x;   // 0 .. Mtot*128-1
    const int m = id >> 7;
    const int g = id & 127;
    const float* p = src + (size_t)m * Dc + g * 8;
    float4 a = *(const float4*)p;
    float4 b = *(const float4*)(p + 4);
    float* q = dst + (size_t)m * Dc + g * 8;
    *(float4*)q       = make_float4(f2tfb(a.x), f2tfb(b.x), f2tfb(a.y), f2tfb(b.y));
    *(float4*)(q + 4) = make_float4(f2tfb(a.z), f2tfb(b.z), f2tfb(a.w), f2tfb(b.w));
}

// ---------------------------------------------------------------------------
// Convert weight [K,N] -> tf32 bits in slab layout:
// (k,n) -> (k>>3)*8192 + (k&3)*2048 + n*2 + ((k>>2)&1)
// ---------------------------------------------------------------------------
__global__ __launch_bounds__(256)
void wconv(const float* __restrict__ src, float* __restrict__ dst)
{
    const int id = blockIdx.x * 256 + threadIdx.x;   // 0 .. 262143
    const int kg   = id >> 11;
    const int slot = (id >> 9) & 3;
    const int np   = id & 511;
    const int k0 = kg * 8 + slot;
    float2 a = *(const float2*)(src + (size_t)k0 * Dc + np * 2);
    float2 b = *(const float2*)(src + (size_t)(k0 + 4) * Dc + np * 2);
    *(float4*)(dst + (size_t)kg * 8192 + slot * 2048 + np * 4) =
        make_float4(f2tfb(a.x), f2tfb(b.x), f2tfb(a.y), f2tfb(b.y));
}

// ---------------------------------------------------------------------------
// tf32 MMA GEMM: C = A[M,1024] @ B[1024,1024] + bias
// A in interleaved-row layout, B in slab layout (both tf32 bits).
// cp.async double-buffered, BK=16; all fragment loads are LDS.64.
// A smem rows stride 24, B smem 8 slabs stride 264: conflict-free uint2 loads.
// EPI 0: out row-major fp32 (+bias)
// EPI 1: Q plain [B,H,S,HD], tf32 bits, *scale
// EPI 2: K [B,H,S,perm(hd)], tf32 bits
// EPI 3: V slab-tiled, tf32 bits
// ---------------------------------------------------------------------------
template <int EPI>
__global__ __launch_bounds__(256)
void mma_gemm(const float* __restrict__ A, const float* __restrict__ B,
              const float* __restrict__ bias, float* __restrict__ C,
              float scale)
{
    constexpr int MI = 4, NI = 4;
    constexpr int Kd = 1024;
    constexpr int ABUF = 128 * 24;   // 3072 floats
    constexpr int BBUF = 8 * 264;    // 2112 floats

    __shared__ __align__(16) float As[2 * ABUF];
    __shared__ __align__(16) float Bs[2 * BBUF];

    const int tid = threadIdx.x;
    const int m0 = blockIdx.y * 128;
    const int n0 = blockIdx.x * 128;

    const int w    = tid >> 5;
    const int lane = tid & 31;
    const int wr   = w & 1;
    const int wc   = w >> 1;
    const int lg   = lane >> 2;
    const int lt   = lane & 3;

    const unsigned abase = (unsigned)__cvta_generic_to_shared(&As[0]);
    const unsigned bbase = (unsigned)__cvta_generic_to_shared(&Bs[0]);

    auto stage = [&](int buf, int k0) {
        // A: 128 rows x 4 chunks (16 floats per row, window k0..k0+15)
#pragma unroll
        for (int i = 0; i < 2; i++) {
            const int c   = tid + i * 256;      // 0..511
            const int row = c >> 2;
            const int c4  = c & 3;
            cpasync16(abase + (unsigned)(buf * ABUF + row * 24 + c4 * 4) * 4,
                      A + (size_t)(m0 + row) * Kd + k0 + c4 * 4);
        }
        // B: 8 slabs x 64 chunks of 16B (256 floats per slab = 128-n slice)
#pragma unroll
        for (int i = 0; i < 2; i++) {
            const int id   = tid + i * 256;     // 0..511
            const int slab = id >> 6;           // 0..7
            const int c    = id & 63;           // 0..63
            const int kg   = (k0 >> 3) + (slab >> 2);
            const int slot = slab & 3;
            cpasync16(bbase + (unsigned)(buf * BBUF + slab * 264 + c * 4) * 4,
                      B + (size_t)kg * 8192 + slot * 2048 + n0 * 2 + c * 4);
        }
    };

    float acc[MI][NI][4];
#pragma unroll
    for (int mi = 0; mi < MI; mi++)
#pragma unroll
        for (int ni = 0; ni < NI; ni++)
#pragma unroll
            for (int r = 0; r < 4; r++) acc[mi][ni][r] = 0.f;

    stage(0, 0);
    asm volatile("cp.async.commit_group;");

    constexpr int NT = Kd / 16;   // 64
#pragma unroll 1
    for (int it = 0; it < NT; it++) {
        const int cur = it & 1;
        if (it + 1 < NT) stage((it + 1) & 1, (it + 1) * 16);
        asm volatile("cp.async.commit_group;");
        asm volatile("cp.async.wait_group 1;");
        __syncthreads();

        const float* Ac  = As + cur * ABUF;
        const float* Bc_ = Bs + cur * BBUF;

#pragma unroll
        for (int kk = 0; kk < 16; kk += 8) {
            unsigned af[MI][4], bf[NI][2];
#pragma unroll
            for (int mi = 0; mi < MI; mi++) {
                const int r = (wr * 64 + mi * 16 + lg) * 24 + kk + lt * 2;
                uint2 lo = *(const uint2*)&Ac[r];
                uint2 hi = *(const uint2*)&Ac[r + 8 * 24];
                af[mi][0] = lo.x; af[mi][1] = hi.x;
                af[mi][2] = lo.y; af[mi][3] = hi.y;
            }
#pragma unroll
            for (int ni = 0; ni < NI; ni++) {
                uint2 p = *(const uint2*)&Bc_[((kk >> 3) * 4 + lt) * 264 +
                                              (wc * 32 + ni * 8 + lg) * 2];
                bf[ni][0] = p.x; bf[ni][1] = p.y;
            }
#pragma unroll
            for (int mi = 0; mi < MI; mi++)
#pragma unroll
                for (int ni = 0; ni < NI; ni++)
                    mma8(acc[mi][ni], af[mi], bf[ni]);
        }
        __syncthreads();
    }

#pragma unroll
    for (int mi = 0; mi < MI; mi++) {
#pragma unroll
        for (int ni = 0; ni < NI; ni++) {
            const int gmb = m0 + wr * 64 + mi * 16 + lg;
            const int gn  = n0 + wc * 32 + ni * 8 + lt * 2;
#pragma unroll
            for (int hh = 0; hh < 2; hh++) {
                const int gm = gmb + hh * 8;
                const float v0 = acc[mi][ni][hh * 2 + 0];
                const float v1 = acc[mi][ni][hh * 2 + 1];
                if (EPI == 0) {
                    *(float2*)&C[(size_t)gm * Dc + gn] =
                        make_float2(v0 + bias[gn], v1 + bias[gn + 1]);
                } else {
                    const float r0 = f2tfb((v0 + bias[gn])     * scale);
                    const float r1 = f2tfb((v1 + bias[gn + 1]) * scale);
                    const int b = gm >> 11, s = gm & 2047;
                    const int hq = gn >> 6, hd = gn & 63;
                    if (EPI == 1) {
                        *(float2*)&C[(((size_t)(b * Hc + hq) * Sc) + s) * HDc + hd] =
                            make_float2(r0, r1);
                    } else if (EPI == 2) {
                        float* base = &C[(((size_t)(b * Hc + hq) * Sc) + s) * HDc];
                        const int p = ((hd >> 3) << 3) + ((hd & 3) << 1) + ((hd >> 2) & 1);
                        base[p]     = r0;
                        base[p + 2] = r1;
                    } else {
                        const int bh = b * Hc + hq;
                        const int t = s >> 5, ww = s & 31;
                        const int slab = ((ww >> 3) << 2) + (ww & 3);
                        const int half = (ww >> 2) & 1;
                        float* base = &C[(size_t)bh * Sc * HDc + t * 2048 + slab * 128 + half];
                        base[hd * 2]       = r0;
                        base[(hd + 1) * 2] = r1;
                    }
                }
            }
        }
    }
}

// ---------------------------------------------------------------------------
// Fused tensor-core flash attention, cp.async double-buffered, LDS.64 frags.
// Block: one (b,h), 128 queries; 8 warps x 16 rows. Key tiles of 32.
// K smem [key][72] pair-interleaved hd; V smem 16 slabs [136].
// __launch_bounds__(256,2) pins <=128 regs (2 CTAs/SM).
// ---------------------------------------------------------------------------
__global__ __launch_bounds__(256, 2)
void fattn(const float* __restrict__ Q, const float* __restrict__ K,
           const float* __restrict__ V, const float* __restrict__ mask,
           float* __restrict__ Octx)
{
    constexpr int TK    = 32;
    constexpr int KST   = 72;    // floats per K row (64 + 8 pad)
    constexpr int VSLAB = 136;   // floats per V slab (128 + 8 pad)

    __shared__ __align__(16) float Ksm[2][TK * KST];
    __shared__ __align__(16) float Vsm[2][16 * VSLAB];
    __shared__ __align__(16) float Msm[2][TK];

    const int tid  = threadIdx.x;
    const int w    = tid >> 5;
    const int lane = tid & 31;
    const int lg   = lane >> 2;
    const int lt   = lane & 3;

    const int bh = blockIdx.y;
    const int b  = bh >> 4;
    const int h  = bh & 15;
    const int q0 = blockIdx.x * 128 + w * 16;

    const float* Kb = K + (size_t)bh * Sc * HDc;
    const float* Vb = V + (size_t)bh * Sc * HDc;
    const float* Mb = mask + (size_t)b * Sc;

    const unsigned kbase = (unsigned)__cvta_generic_to_shared(&Ksm[0][0]);
    const unsigned vbase = (unsigned)__cvta_generic_to_shared(&Vsm[0][0]);
    const unsigned mbase = (unsigned)__cvta_generic_to_shared(&Msm[0][0]);

    // Q fragments (plain layout, tf32 bits)
    const float* Qb = Q + ((size_t)bh * Sc + q0) * HDc;
    unsigned qf[8][4];
#pragma unroll
    for (int kf = 0; kf < 8; kf++) {
        qf[kf][0] = __float_as_uint(__ldg(Qb + (size_t)(lg    ) * HDc + kf * 8 + lt    ));
        qf[kf][1] = __float_as_uint(__ldg(Qb + (size_t)(lg + 8) * HDc + kf * 8 + lt    ));
        qf[kf][2] = __float_as_uint(__ldg(Qb + (size_t)(lg    ) * HDc + kf * 8 + lt + 4));
        qf[kf][3] = __float_as_uint(__ldg(Qb + (size_t)(lg + 8) * HDc + kf * 8 + lt + 4));
    }

    float acc_o[8][4];
#pragma unroll
    for (int no = 0; no < 8; no++)
#pragma unroll
        for (int r = 0; r < 4; r++) acc_o[no][r] = 0.f;
    float m_lo = -1e30f, m_hi = -1e30f, l_lo = 0.f, l_hi = 0.f;

    auto stage = [&](int buf, int kt) {
#pragma unroll
        for (int i = 0; i < 2; i++) {
            const int id = tid + i * 256;        // 0..511
            {   // K: 32 rows x 16 chunks
                const int key = id >> 4;
                const int c4  = id & 15;
                cpasync16(kbase + (unsigned)(buf * TK * KST + key * KST + c4 * 4) * 4,
                          Kb + (size_t)(kt + key) * HDc + c4 * 4);
            }
            {   // V: 16 slabs x 32 chunks (tile = 2048 contiguous floats)
                const int slab = id >> 5;
                const int c    = id & 31;
                cpasync16(vbase + (unsigned)(buf * 16 * VSLAB + slab * VSLAB + c * 4) * 4,
                          Vb + (size_t)(kt >> 5) * 2048 + slab * 128 + c * 4);
            }
        }
        if (tid < 8)
            cpasync16(mbase + (unsigned)(buf * TK + tid * 4) * 4, Mb + kt + tid * 4);
    };

    stage(0, 0);
    asm volatile("cp.async.commit_group;");

    constexpr int NT = Sc / TK;   // 64
#pragma unroll 1
    for (int it = 0; it < NT; it++) {
        const int cur = it & 1;
        if (it + 1 < NT) stage((it + 1) & 1, (it + 1) * TK);
        asm volatile("cp.async.commit_group;");
        asm volatile("cp.async.wait_group 1;");
        __syncthreads();

        const float* Kc = Ksm[cur];
        const float* Vc = Vsm[cur];
        const float* Mc = Msm[cur];

        // ---- S = Q K^T : LDS.64 B-fragments ----
        float sc[4][4];
#pragma unroll
        for (int ni = 0; ni < 4; ni++)
#pragma unroll
            for (int r = 0; r < 4; r++) sc[ni][r] = 0.f;
#pragma unroll
        for (int kf = 0; kf < 8; kf++) {
#pragma unroll
            for (int ni = 0; ni < 4; ni++) {
                uint2 p = *(const uint2*)&Kc[(ni * 8 + lg) * KST + (kf * 4 + lt) * 2];
                unsigned bf[2] = { p.x, p.y };
                mma8(sc[ni], qf[kf], bf);
            }
        }

        // ---- mask + online softmax (quad-local) ----
        float rmax_lo = -1e30f, rmax_hi = -1e30f;
#pragma unroll
        for (int ni = 0; ni < 4; ni++) {
            const float mk0 = Mc[ni * 8 + 2 * lt];
            const float mk1 = Mc[ni * 8 + 2 * lt + 1];
            sc[ni][0] += mk0; sc[ni][1] += mk1;
            sc[ni][2] += mk0; sc[ni][3] += mk1;
            rmax_lo = fmaxf(rmax_lo, fmaxf(sc[ni][0], sc[ni][1]));
            rmax_hi = fmaxf(rmax_hi, fmaxf(sc[ni][2], sc[ni][3]));
        }
        rmax_lo = fmaxf(rmax_lo, __shfl_xor_sync(0xffffffffu, rmax_lo, 1));
        rmax_lo = fmaxf(rmax_lo, __shfl_xor_sync(0xffffffffu, rmax_lo, 2));
        rmax_hi = fmaxf(rmax_hi, __shfl_xor_sync(0xffffffffu, rmax_hi, 1));
        rmax_hi = fmaxf(rmax_hi, __shfl_xor_sync(0xffffffffu, rmax_hi, 2));

        const float mn_lo = fmaxf(m_lo, rmax_lo);
        const float mn_hi = fmaxf(m_hi, rmax_hi);
        const float al_lo = __expf(m_lo - mn_lo);
        const float al_hi = __expf(m_hi - mn_hi);
        m_lo = mn_lo; m_hi = mn_hi;

        float ps_lo = 0.f, ps_hi = 0.f;
#pragma unroll
        for (int ni = 0; ni < 4; ni++) {
            sc[ni][0] = __expf(sc[ni][0] - m_lo);
            sc[ni][1] = __expf(sc[ni][1] - m_lo);
            sc[ni][2] = __expf(sc[ni][2] - m_hi);
            sc[ni][3] = __expf(sc[ni][3] - m_hi);
            ps_lo += sc[ni][0] + sc[ni][1];
            ps_hi += sc[ni][2] + sc[ni][3];
        }
        l_lo = l_lo * al_lo + ps_lo;
        l_hi = l_hi * al_hi + ps_hi;
#pragma unroll
        for (int no = 0; no < 8; no++) {
            acc_o[no][0] *= al_lo; acc_o[no][1] *= al_lo;
            acc_o[no][2] *= al_hi; acc_o[no][3] *= al_hi;
        }

        // ---- PV: P C-frag -> A-frag via shuffles; LDS.64 V-fragments ----
        const int src_lo = (lane & 28) | (lt >> 1);
        const int src_hi = src_lo + 2;
#pragma unroll
        for (int kf = 0; kf < 4; kf++) {
            unsigned a[4];
            {
                float v0 = __shfl_sync(0xffffffffu, sc[kf][0], src_lo);
                float v1 = __shfl_sync(0xffffffffu, sc[kf][1], src_lo);
                a[0] = f2tf((lt & 1) ? v1 : v0);
                float v2 = __shfl_sync(0xffffffffu, sc[kf][2], src_lo);
                float v3 = __shfl_sync(0xffffffffu, sc[kf][3], src_lo);
                a[1] = f2tf((lt & 1) ? v3 : v2);
                float u0 = __shfl_sync(0xffffffffu, sc[kf][0], src_hi);
                float u1 = __shfl_sync(0xffffffffu, sc[kf][1], src_hi);
                a[2] = f2tf((lt & 1) ? u1 : u0);
                float u2 = __shfl_sync(0xffffffffu, sc[kf][2], src_hi);
                float u3 = __shfl_sync(0xffffffffu, sc[kf][3], src_hi);
                a[3] = f2tf((lt & 1) ? u3 : u2);
            }
            const int sbase = (kf * 4 + lt) * VSLAB;
#pragma unroll
            for (int no = 0; no < 8; no++) {
                uint2 p = *(const uint2*)&Vc[sbase + (no * 8 + lg) * 2];
                unsigned bf[2] = { p.x, p.y };
                mma8(acc_o[no], a, bf);
            }
        }
        __syncthreads();
    }

    l_lo += __shfl_xor_sync(0xffffffffu, l_lo, 1);
    l_lo += __shfl_xor_sync(0xffffffffu, l_lo, 2);
    l_hi += __shfl_xor_sync(0xffffffffu, l_hi, 1);
    l_hi += __shfl_xor_sync(0xffffffffu, l_hi, 2);
    const float inv_lo = 1.f / l_lo;
    const float inv_hi = 1.f / l_hi;

    // write ctx as tf32 bits, pre-interleaved for the output-projection GEMM
    float* Ob = Octx + ((size_t)b * Sc + q0) * Dc + h * HDc;
    const int p0 = (lt & 1) * 4 + (lt >> 1);   // perm of col 2*lt within 8-group
#pragma unroll
    for (int no = 0; no < 8; no++) {
        const int pb = no * 8 + p0;
        Ob[(size_t)(lg    ) * Dc + pb    ] = f2tfb(acc_o[no][0] * inv_lo);
        Ob[(size_t)(lg    ) * Dc + pb + 2] = f2tfb(acc_o[no][1] * inv_lo);
        Ob[(size_t)(lg + 8) * Dc + pb    ] = f2tfb(acc_o[no][2] * inv_hi);
        Ob[(size_t)(lg + 8) * Dc + pb + 2] = f2tfb(acc_o[no][3] * inv_hi);
    }
}

// ---------------------------------------------------------------------------
extern "C" void kernel_launch(void* const* d_in, const int* in_sizes, int n_in,
                              void* d_out, int out_size)
{
    const float* x    = (const float*)d_in[0];
    const float* mask = (const float*)d_in[1];
    const float* Wq   = (const float*)d_in[2];
    const float* bq   = (const float*)d_in[3];
    const float* Wk   = (const float*)d_in[4];
    const float* bk   = (const float*)d_in[5];
    const float* Wv   = (const float*)d_in[6];
    const float* bv   = (const float*)d_in[7];
    const float* Wo   = (const float*)d_in[8];
    const float* bo   = (const float*)d_in[9];
    float* out = (float*)d_out;

    void *qv, *kv, *vv, *cv, *xtv, *wqv, *wkv, *wvv, *wov;
    cudaGetSymbolAddress(&qv,  g_q);
    cudaGetSymbolAddress(&kv,  g_k);
    cudaGetSymbolAddress(&vv,  g_v);
    cudaGetSymbolAddress(&cv,  g_ctx);
    cudaGetSymbolAddress(&xtv, g_xt);
    cudaGetSymbolAddress(&wqv, g_wq);
    cudaGetSymbolAddress(&wkv, g_wk);
    cudaGetSymbolAddress(&wvv, g_wv);
    cudaGetSymbolAddress(&wov, g_wo);
    float* q   = (float*)qv;
    float* k   = (float*)kv;
    float* v   = (float*)vv;
    float* ctx = (float*)cv;
    float* xt  = (float*)xtv;
    float* wq  = (float*)wqv;
    float* wk  = (float*)wkv;
    float* wv  = (float*)wvv;
    float* wo  = (float*)wov;

    // Pre-round + pre-interleave inputs (bit-identical rounding positions)
    xconv<<<(Mtot * 128) / 256, 256>>>(x, xt);       // 2048 blocks
    wconv<<<1024, 256>>>(Wq, wq);
    wconv<<<1024, 256>>>(Wk, wk);
    wconv<<<1024, 256>>>(Wv, wv);
    wconv<<<1024, 256>>>(Wo, wo);

    dim3 g1(Dc / 128, Mtot / 128);   // (8, 32)
    mma_gemm<1><<<g1, 256>>>(xt, wq, bq, q, 0.125f);   // Q (1/sqrt(64))
    mma_gemm<2><<<g1, 256>>>(xt, wk, bk, k, 1.0f);     // K (hd-interleaved)
    mma_gemm<3><<<g1, 256>>>(xt, wv, bv, v, 1.0f);     // V (slab-tiled)

    fattn<<<dim3(Sc / 128, Bc * Hc), 256>>>(q, k, v, mask, ctx);

    mma_gemm<0><<<g1, 256>>>(ctx, wo, bo, out, 1.0f);  // output projection
}